// round 3
// baseline (speedup 1.0000x reference)
#include <cuda_runtime.h>
#include <math.h>

#define T_STEPS 1024
#define HID     256
#define G4      1024          // 4*HID
#define NSPK    1251
#define CPL     32            // CTAs per layer
#define UPC     8             // units per CTA
#define RPC     32            // rows per CTA (UPC*4)
#define KSL     32            // k-slice per thread (256/8)

// -------- device scratch (no allocations allowed) --------
__device__ float g_h[3][T_STEPS + 1][HID];     // h history per layer
__device__ int   g_cnt[3][T_STEPS + 1];        // completion counters
__device__ float g_xg0[T_STEPS][G4];           // layer-0 input projections (+biases)
__device__ float g_logits[T_STEPS][NSPK];      // pre-softmax logits

// ============================================================
// Reset kernel: zero counters / initial h. Runs first each launch.
// ============================================================
__global__ void reset_kernel() {
    int idx = blockIdx.x * blockDim.x + threadIdx.x;
    if (idx < 3 * (T_STEPS + 1)) {
        int l = idx / (T_STEPS + 1);
        int t = idx % (T_STEPS + 1);
        g_cnt[l][t] = (t == 0) ? CPL : 0;
    }
    if (idx < 3 * HID) {
        int l = idx / HID;
        int u = idx % HID;
        g_h[l][0][u] = 0.f;
    }
}

// ============================================================
// Layer-0 input projection: xg0[t][g] = b_ih0[g]+b_hh0[g] + x[63,t,:]·w_ih0[g,:]
// ============================================================
__global__ void xg0_kernel(const float* __restrict__ x,
                           const float* __restrict__ w_ih0,
                           const float* __restrict__ b_ih0,
                           const float* __restrict__ b_hh0) {
    int t   = blockIdx.x;
    int tid = threadIdx.x;
    __shared__ float xr[40];
    if (tid < 40) xr[tid] = x[(63 * T_STEPS + t) * 40 + tid];
    __syncthreads();
#pragma unroll
    for (int q = 0; q < 4; q++) {
        int g = q * 256 + tid;
        float acc = b_ih0[g] + b_hh0[g];
        const float* w = w_ih0 + g * 40;
#pragma unroll
        for (int f = 0; f < 40; f++) acc = fmaf(w[f], xr[f], acc);
        g_xg0[t][g] = acc;
    }
}

// ============================================================
// Persistent wavefront LSTM kernel. 96 CTAs (3 layers x 32), 256 thr.
// Thread (r = tid>>3, kp = tid&7): row r of this CTA, k-slice kp*32..+32.
// Row r -> gate q = r>>3, local unit ul = r&7; global row = q*256 + base_u + ul.
// Weights register-resident. h staged to smem with 4-word pad per 32-word
// window -> conflict-free broadcast float4 LDS.
// Poll loops spin hot briefly, then back off with __nanosleep to avoid
// livelocking the NOC if a producer is ever delayed.
// ============================================================
__device__ __forceinline__ float sigmoidf_(float v) {
    return 1.f / (1.f + __expf(-v));
}

__device__ __forceinline__ void poll_cnt(const int* p) {
    int spins = 0;
    while (__ldcg(p) < CPL) {
        if (++spins > 64) { __nanosleep(64); }
    }
}

__global__ void __launch_bounds__(256, 1)
lstm_kernel(const float* __restrict__ w_hh0,
            const float* __restrict__ w_ih1, const float* __restrict__ w_hh1,
            const float* __restrict__ b_ih1, const float* __restrict__ b_hh1,
            const float* __restrict__ w_ih2, const float* __restrict__ w_hh2,
            const float* __restrict__ b_ih2, const float* __restrict__ b_hh2) {
    const int l      = blockIdx.x / CPL;
    const int cidx   = blockIdx.x % CPL;
    const int base_u = cidx * UPC;
    const int tid    = threadIdx.x;
    const int r      = tid >> 3;
    const int kp     = tid & 7;
    const int q      = r >> 3;
    const int ul     = r & 7;
    const int grow   = q * 256 + base_u + ul;

    const float* Whh = (l == 0) ? w_hh0 : (l == 1) ? w_hh1 : w_hh2;
    const float* Wih = (l == 1) ? w_ih1 : w_ih2;
    const float* Bih = (l == 1) ? b_ih1 : b_ih2;
    const float* Bhh = (l == 1) ? b_hh1 : b_hh2;

    // ---- load weight slices into registers (one-time) ----
    float whh[KSL];
    float wih[KSL];
    {
        const float* wr = Whh + grow * HID + kp * KSL;
#pragma unroll
        for (int j = 0; j < KSL / 4; j++) {
            float4 v = *(const float4*)(wr + 4 * j);
            whh[4 * j + 0] = v.x; whh[4 * j + 1] = v.y;
            whh[4 * j + 2] = v.z; whh[4 * j + 3] = v.w;
        }
    }
    if (l > 0) {
        const float* wr = Wih + grow * HID + kp * KSL;
#pragma unroll
        for (int j = 0; j < KSL / 4; j++) {
            float4 v = *(const float4*)(wr + 4 * j);
            wih[4 * j + 0] = v.x; wih[4 * j + 1] = v.y;
            wih[4 * j + 2] = v.z; wih[4 * j + 3] = v.w;
        }
    } else {
#pragma unroll
        for (int j = 0; j < KSL; j++) wih[j] = 0.f;
    }

    // bias sums for the 8 unit-updating threads (layers 1,2)
    float xb0 = 0.f, xb1 = 0.f, xb2 = 0.f, xb3 = 0.f;
    if (l > 0 && tid < UPC) {
        xb0 = Bih[0 * 256 + base_u + tid] + Bhh[0 * 256 + base_u + tid];
        xb1 = Bih[1 * 256 + base_u + tid] + Bhh[1 * 256 + base_u + tid];
        xb2 = Bih[2 * 256 + base_u + tid] + Bhh[2 * 256 + base_u + tid];
        xb3 = Bih[3 * 256 + base_u + tid] + Bhh[3 * 256 + base_u + tid];
    }

    __shared__ float sm_hA[8 * 36];  // padded: word(k) = k + 4*(k>>5)
    __shared__ float sm_hB[8 * 36];
    __shared__ float gsum[RPC];

    float c_state = 0.f;

    for (int t = 1; t <= T_STEPS; t++) {
        // prefetch layer-0 xg (no dependency on h)
        float px0 = 0.f, px1 = 0.f, px2 = 0.f, px3 = 0.f;
        if (l == 0 && tid < UPC) {
            px0 = __ldg(&g_xg0[t - 1][0 * 256 + base_u + tid]);
            px1 = __ldg(&g_xg0[t - 1][1 * 256 + base_u + tid]);
            px2 = __ldg(&g_xg0[t - 1][2 * 256 + base_u + tid]);
            px3 = __ldg(&g_xg0[t - 1][3 * 256 + base_u + tid]);
        }
        // ---- poll producers ----
        if (tid == 0) {
            poll_cnt(&g_cnt[l][t - 1]);
            __threadfence();
        }
        if (l > 0 && tid == 32) {
            poll_cnt(&g_cnt[l - 1][t]);
            __threadfence();
        }
        __syncthreads();
        // ---- stage h vectors into padded smem ----
        if (tid < 64) {
            float4 v = __ldcg((const float4*)&g_h[l][t - 1][4 * tid]);
            int w = 4 * tid + 4 * (tid >> 3);
            *(float4*)&sm_hA[w] = v;
        } else if (l > 0 && tid < 128) {
            int i = tid - 64;
            float4 v = __ldcg((const float4*)&g_h[l - 1][t][4 * i]);
            int w = 4 * i + 4 * (i >> 3);
            *(float4*)&sm_hB[w] = v;
        }
        __syncthreads();
        // ---- matvec slice ----
        float acc = 0.f;
        const int base = kp * 36;
#pragma unroll
        for (int j = 0; j < 8; j++) {
            float4 hv = *(const float4*)&sm_hA[base + 4 * j];
            acc = fmaf(whh[4 * j + 0], hv.x, acc);
            acc = fmaf(whh[4 * j + 1], hv.y, acc);
            acc = fmaf(whh[4 * j + 2], hv.z, acc);
            acc = fmaf(whh[4 * j + 3], hv.w, acc);
        }
        if (l > 0) {
#pragma unroll
            for (int j = 0; j < 8; j++) {
                float4 hv = *(const float4*)&sm_hB[base + 4 * j];
                acc = fmaf(wih[4 * j + 0], hv.x, acc);
                acc = fmaf(wih[4 * j + 1], hv.y, acc);
                acc = fmaf(wih[4 * j + 2], hv.z, acc);
                acc = fmaf(wih[4 * j + 3], hv.w, acc);
            }
        }
        // 8-way reduce across kp (lane bits 0..2)
        acc += __shfl_xor_sync(0xffffffffu, acc, 1);
        acc += __shfl_xor_sync(0xffffffffu, acc, 2);
        acc += __shfl_xor_sync(0xffffffffu, acc, 4);
        if (kp == 0) gsum[r] = acc;
        __syncthreads();
        // ---- gate nonlinearity + cell update (8 threads) ----
        if (tid < UPC) {
            float gi = gsum[0 * 8 + tid] + ((l == 0) ? px0 : xb0);
            float gf = gsum[1 * 8 + tid] + ((l == 0) ? px1 : xb1);
            float gg = gsum[2 * 8 + tid] + ((l == 0) ? px2 : xb2);
            float go = gsum[3 * 8 + tid] + ((l == 0) ? px3 : xb3);
            gi = sigmoidf_(gi);
            gf = sigmoidf_(gf);
            gg = tanhf(gg);
            go = sigmoidf_(go);
            c_state = fmaf(gf, c_state, gi * gg);
            float h = go * tanhf(c_state);
            g_h[l][t][base_u + tid] = h;
            __threadfence();
            __syncwarp(0x000000ffu);
            if (tid == 0) atomicAdd(&g_cnt[l][t], 1);
        }
    }
}

// ============================================================
// Final linear: logits[t][n] = b_lin[n] + h2[t]·w_lin[n]
// 64x64 tiles, k-chunks of 32, 256 threads, acc 4x4 per thread.
// ============================================================
__global__ void lin_kernel(const float* __restrict__ w_lin,
                           const float* __restrict__ b_lin) {
    const int n0  = blockIdx.x * 64;
    const int t0  = blockIdx.y * 64;
    const int tid = threadIdx.x;
    const int ti  = tid & 15;   // t sub-index
    const int nj  = tid >> 4;   // n sub-index

    __shared__ float As[64][36];
    __shared__ float Bs[64][36];

    float acc[4][4];
#pragma unroll
    for (int m = 0; m < 4; m++)
#pragma unroll
        for (int n = 0; n < 4; n++) acc[m][n] = 0.f;

    const int lrow = tid >> 2;
    const int lc0  = (tid & 3) * 8;

    for (int kc = 0; kc < HID; kc += 32) {
        {
            const float* src = &g_h[2][t0 + lrow + 1][kc + lc0];
            float4 v0 = *(const float4*)src;
            float4 v1 = *(const float4*)(src + 4);
            *(float4*)&As[lrow][lc0]     = v0;
            *(float4*)&As[lrow][lc0 + 4] = v1;
        }
        {
            int n = n0 + lrow;
            float4 v0 = make_float4(0.f, 0.f, 0.f, 0.f);
            float4 v1 = make_float4(0.f, 0.f, 0.f, 0.f);
            if (n < NSPK) {
                const float* src = &w_lin[n * HID + kc + lc0];
                v0 = *(const float4*)src;
                v1 = *(const float4*)(src + 4);
            }
            *(float4*)&Bs[lrow][lc0]     = v0;
            *(float4*)&Bs[lrow][lc0 + 4] = v1;
        }
        __syncthreads();
#pragma unroll
        for (int kk = 0; kk < 32; kk++) {
            float a[4], b[4];
#pragma unroll
            for (int m = 0; m < 4; m++) a[m] = As[ti + 16 * m][kk];
#pragma unroll
            for (int n = 0; n < 4; n++) b[n] = Bs[nj + 16 * n][kk];
#pragma unroll
            for (int m = 0; m < 4; m++)
#pragma unroll
                for (int n = 0; n < 4; n++)
                    acc[m][n] = fmaf(a[m], b[n], acc[m][n]);
        }
        __syncthreads();
    }
#pragma unroll
    for (int m = 0; m < 4; m++) {
        int t = t0 + ti + 16 * m;
#pragma unroll
        for (int n = 0; n < 4; n++) {
            int nn = n0 + nj + 16 * n;
            if (nn < NSPK) g_logits[t][nn] = acc[m][n] + b_lin[nn];
        }
    }
}

// ============================================================
// Row-wise log_softmax over NSPK, one block per t.
// ============================================================
__global__ void lsm_kernel(float* __restrict__ out) {
    const int t   = blockIdx.x;
    const int tid = threadIdx.x;
    const int lane = tid & 31;
    const int wid  = tid >> 5;

    float v[5];
    float mx = -INFINITY;
#pragma unroll
    for (int m = 0; m < 5; m++) {
        int n = tid + m * 256;
        v[m] = (n < NSPK) ? g_logits[t][n] : -INFINITY;
        mx = fmaxf(mx, v[m]);
    }
    __shared__ float smax[8];
    __shared__ float ssum[8];
#pragma unroll
    for (int o = 16; o > 0; o >>= 1) mx = fmaxf(mx, __shfl_xor_sync(0xffffffffu, mx, o));
    if (lane == 0) smax[wid] = mx;
    __syncthreads();
    mx = smax[0];
#pragma unroll
    for (int w = 1; w < 8; w++) mx = fmaxf(mx, smax[w]);

    float s = 0.f;
#pragma unroll
    for (int m = 0; m < 5; m++) {
        int n = tid + m * 256;
        if (n < NSPK) s += __expf(v[m] - mx);
    }
#pragma unroll
    for (int o = 16; o > 0; o >>= 1) s += __shfl_xor_sync(0xffffffffu, s, o);
    if (lane == 0) ssum[wid] = s;
    __syncthreads();
    s = ssum[0];
#pragma unroll
    for (int w = 1; w < 8; w++) s += ssum[w];

    float lg = logf(s) + mx;
#pragma unroll
    for (int m = 0; m < 5; m++) {
        int n = tid + m * 256;
        if (n < NSPK) out[t * NSPK + n] = v[m] - lg;
    }
}

// ============================================================
extern "C" void kernel_launch(void* const* d_in, const int* in_sizes, int n_in,
                              void* d_out, int out_size) {
    const float* x     = (const float*)d_in[0];
    const float* w_ih0 = (const float*)d_in[1];
    const float* w_hh0 = (const float*)d_in[2];
    const float* b_ih0 = (const float*)d_in[3];
    const float* b_hh0 = (const float*)d_in[4];
    const float* w_ih1 = (const float*)d_in[5];
    const float* w_hh1 = (const float*)d_in[6];
    const float* b_ih1 = (const float*)d_in[7];
    const float* b_hh1 = (const float*)d_in[8];
    const float* w_ih2 = (const float*)d_in[9];
    const float* w_hh2 = (const float*)d_in[10];
    const float* b_ih2 = (const float*)d_in[11];
    const float* b_hh2 = (const float*)d_in[12];
    const float* w_lin = (const float*)d_in[13];
    const float* b_lin = (const float*)d_in[14];

    reset_kernel<<<13, 256>>>();
    xg0_kernel<<<T_STEPS, 256>>>(x, w_ih0, b_ih0, b_hh0);
    lstm_kernel<<<3 * CPL, 256>>>(w_hh0, w_ih1, w_hh1, b_ih1, b_hh1,
                                  w_ih2, w_hh2, b_ih2, b_hh2);
    dim3 gl((NSPK + 63) / 64, T_STEPS / 64);
    lin_kernel<<<gl, 256>>>(w_lin, b_lin);
    lsm_kernel<<<T_STEPS, 256>>>((float*)d_out);
}

// round 5
// speedup vs baseline: 1.9403x; 1.9403x over previous
#include <cuda_runtime.h>
#include <math.h>

#define T_STEPS 1024
#define HID     256
#define G4      1024          // 4*HID
#define NSPK    1251
#define CPL     32            // CTAs per layer
#define UPC     8             // units per CTA
#define RPC     32            // rows per CTA (UPC*4)
#define KSL     32            // k-slice per thread (256/8)

// -------- device scratch (no allocations allowed) --------
__device__ float g_h[3][T_STEPS + 1][HID];     // h history per layer (NaN = not yet written)
__device__ float g_xg0[T_STEPS][G4];           // layer-0 input projections (+biases)
__device__ float g_logits[T_STEPS][NSPK];      // pre-softmax logits

#define SENT_BITS 0x7FC00001u

// ============================================================
// Reset kernel: t=0 rows -> 0.0f, t>=1 rows -> NaN sentinel.
// ============================================================
__global__ void reset_kernel() {
    int idx = blockIdx.x * blockDim.x + threadIdx.x;
    const int per = (T_STEPS + 1) * HID;
    const int total = 3 * per;
    if (idx < total) {
        int rem = idx % per;
        int t = rem / HID;
        ((unsigned*)g_h)[idx] = (t == 0) ? 0u : SENT_BITS;
    }
}

// ============================================================
// Layer-0 input projection: xg0[t][g] = b_ih0[g]+b_hh0[g] + x[63,t,:]·w_ih0[g,:]
// ============================================================
__global__ void xg0_kernel(const float* __restrict__ x,
                           const float* __restrict__ w_ih0,
                           const float* __restrict__ b_ih0,
                           const float* __restrict__ b_hh0) {
    int t   = blockIdx.x;
    int tid = threadIdx.x;
    __shared__ float xr[40];
    if (tid < 40) xr[tid] = x[(63 * T_STEPS + t) * 40 + tid];
    __syncthreads();
#pragma unroll
    for (int q = 0; q < 4; q++) {
        int g = q * 256 + tid;
        float acc = b_ih0[g] + b_hh0[g];
        const float* w = w_ih0 + g * 40;
#pragma unroll
        for (int f = 0; f < 40; f++) acc = fmaf(w[f], xr[f], acc);
        g_xg0[t][g] = acc;
    }
}

// ============================================================
// Data-polling load: spin on a float4 until it contains no NaN sentinel.
// Each 4B store is atomic; each component is checked independently, so no
// fences / flags / atomics are needed anywhere in the exchange.
// ============================================================
__device__ __forceinline__ float4 poll4(const float* p) {
    float x, y, z, w;
    int spins = 0;
    for (;;) {
        asm volatile("ld.global.cg.v4.f32 {%0,%1,%2,%3},[%4];"
                     : "=f"(x), "=f"(y), "=f"(z), "=f"(w) : "l"(p));
        if (!(x != x || y != y || z != z || w != w)) break;
        if (++spins > 4096) { __nanosleep(64); }   // safety valve only
    }
    return make_float4(x, y, z, w);
}

__device__ __forceinline__ float sigmoidf_(float v) {
    return 1.f / (1.f + __expf(-v));
}

// ============================================================
// Persistent wavefront LSTM kernel. 96 CTAs (3 layers x 32), 256 thr.
// Thread (r = tid>>3, kp = tid&7): row r of this CTA, k-slice kp*32..+32.
// Row r -> gate q = r>>3, local unit ul = r&7; global row = q*256 + base_u + ul.
// Weights register-resident. h staged to smem with 4-word pad per 32-word
// window -> conflict-free broadcast float4 LDS.
// ============================================================
__global__ void __launch_bounds__(256, 1)
lstm_kernel(const float* __restrict__ w_hh0,
            const float* __restrict__ w_ih1, const float* __restrict__ w_hh1,
            const float* __restrict__ b_ih1, const float* __restrict__ b_hh1,
            const float* __restrict__ w_ih2, const float* __restrict__ w_hh2,
            const float* __restrict__ b_ih2, const float* __restrict__ b_hh2) {
    const int l      = blockIdx.x / CPL;
    const int cidx   = blockIdx.x % CPL;
    const int base_u = cidx * UPC;
    const int tid    = threadIdx.x;
    const int r      = tid >> 3;
    const int kp     = tid & 7;
    const int q      = r >> 3;
    const int ul     = r & 7;
    const int grow   = q * 256 + base_u + ul;

    const float* Whh = (l == 0) ? w_hh0 : (l == 1) ? w_hh1 : w_hh2;
    const float* Wih = (l == 1) ? w_ih1 : w_ih2;
    const float* Bih = (l == 1) ? b_ih1 : b_ih2;
    const float* Bhh = (l == 1) ? b_hh1 : b_hh2;

    // ---- load weight slices into registers (one-time) ----
    float whh[KSL];
    float wih[KSL];
    {
        const float* wr = Whh + grow * HID + kp * KSL;
#pragma unroll
        for (int j = 0; j < KSL / 4; j++) {
            float4 v = *(const float4*)(wr + 4 * j);
            whh[4 * j + 0] = v.x; whh[4 * j + 1] = v.y;
            whh[4 * j + 2] = v.z; whh[4 * j + 3] = v.w;
        }
    }
    if (l > 0) {
        const float* wr = Wih + grow * HID + kp * KSL;
#pragma unroll
        for (int j = 0; j < KSL / 4; j++) {
            float4 v = *(const float4*)(wr + 4 * j);
            wih[4 * j + 0] = v.x; wih[4 * j + 1] = v.y;
            wih[4 * j + 2] = v.z; wih[4 * j + 3] = v.w;
        }
    } else {
#pragma unroll
        for (int j = 0; j < KSL; j++) wih[j] = 0.f;
    }

    // bias sums for the 8 unit-updating threads (layers 1,2)
    float xb0 = 0.f, xb1 = 0.f, xb2 = 0.f, xb3 = 0.f;
    if (l > 0 && tid < UPC) {
        xb0 = Bih[0 * 256 + base_u + tid] + Bhh[0 * 256 + base_u + tid];
        xb1 = Bih[1 * 256 + base_u + tid] + Bhh[1 * 256 + base_u + tid];
        xb2 = Bih[2 * 256 + base_u + tid] + Bhh[2 * 256 + base_u + tid];
        xb3 = Bih[3 * 256 + base_u + tid] + Bhh[3 * 256 + base_u + tid];
    }

    __shared__ float sm_hA[8 * 36];  // padded: word(k) = k + 4*(k>>5)
    __shared__ float sm_hB[8 * 36];
    __shared__ float gsum[RPC];

    float c_state = 0.f;

    for (int t = 1; t <= T_STEPS; t++) {
        // prefetch layer-0 xg (no dependency on h) — in flight during the poll
        float px0 = 0.f, px1 = 0.f, px2 = 0.f, px3 = 0.f;
        if (l == 0 && tid < UPC) {
            px0 = __ldg(&g_xg0[t - 1][0 * 256 + base_u + tid]);
            px1 = __ldg(&g_xg0[t - 1][1 * 256 + base_u + tid]);
            px2 = __ldg(&g_xg0[t - 1][2 * 256 + base_u + tid]);
            px3 = __ldg(&g_xg0[t - 1][3 * 256 + base_u + tid]);
        }
        // ---- poll-load h vectors straight into padded smem ----
        if (tid < 64) {
            float4 v = poll4(&g_h[l][t - 1][4 * tid]);
            int w = 4 * tid + 4 * (tid >> 3);
            *(float4*)&sm_hA[w] = v;
        } else if (l > 0 && tid < 128) {
            int i = tid - 64;
            float4 v = poll4(&g_h[l - 1][t][4 * i]);
            int w = 4 * i + 4 * (i >> 3);
            *(float4*)&sm_hB[w] = v;
        }
        __syncthreads();
        // ---- matvec slice (2 accumulators for shorter dependent chains) ----
        float a0 = 0.f, a1 = 0.f;
        const int base = kp * 36;
#pragma unroll
        for (int j = 0; j < 4; j++) {
            float4 h0 = *(const float4*)&sm_hA[base + 8 * j];
            float4 h1 = *(const float4*)&sm_hA[base + 8 * j + 4];
            a0 = fmaf(whh[8 * j + 0], h0.x, a0);
            a0 = fmaf(whh[8 * j + 1], h0.y, a0);
            a0 = fmaf(whh[8 * j + 2], h0.z, a0);
            a0 = fmaf(whh[8 * j + 3], h0.w, a0);
            a1 = fmaf(whh[8 * j + 4], h1.x, a1);
            a1 = fmaf(whh[8 * j + 5], h1.y, a1);
            a1 = fmaf(whh[8 * j + 6], h1.z, a1);
            a1 = fmaf(whh[8 * j + 7], h1.w, a1);
        }
        if (l > 0) {
#pragma unroll
            for (int j = 0; j < 4; j++) {
                float4 h0 = *(const float4*)&sm_hB[base + 8 * j];
                float4 h1 = *(const float4*)&sm_hB[base + 8 * j + 4];
                a0 = fmaf(wih[8 * j + 0], h0.x, a0);
                a0 = fmaf(wih[8 * j + 1], h0.y, a0);
                a0 = fmaf(wih[8 * j + 2], h0.z, a0);
                a0 = fmaf(wih[8 * j + 3], h0.w, a0);
                a1 = fmaf(wih[8 * j + 4], h1.x, a1);
                a1 = fmaf(wih[8 * j + 5], h1.y, a1);
                a1 = fmaf(wih[8 * j + 6], h1.z, a1);
                a1 = fmaf(wih[8 * j + 7], h1.w, a1);
            }
        }
        float acc = a0 + a1;
        // 8-way reduce across kp (lane bits 0..2)
        acc += __shfl_xor_sync(0xffffffffu, acc, 1);
        acc += __shfl_xor_sync(0xffffffffu, acc, 2);
        acc += __shfl_xor_sync(0xffffffffu, acc, 4);
        if (kp == 0) gsum[r] = acc;
        __syncthreads();
        // ---- gate nonlinearity + cell update (8 threads), plain STG publish ----
        if (tid < UPC) {
            float gi = gsum[0 * 8 + tid] + ((l == 0) ? px0 : xb0);
            float gf = gsum[1 * 8 + tid] + ((l == 0) ? px1 : xb1);
            float gg = gsum[2 * 8 + tid] + ((l == 0) ? px2 : xb2);
            float go = gsum[3 * 8 + tid] + ((l == 0) ? px3 : xb3);
            gi = sigmoidf_(gi);
            gf = sigmoidf_(gf);
            gg = tanhf(gg);
            go = sigmoidf_(go);
            c_state = fmaf(gf, c_state, gi * gg);
            float h = go * tanhf(c_state);
            g_h[l][t][base_u + tid] = h;   // value IS the flag (sentinel scheme)
        }
        __syncthreads();   // protect smem reuse next iteration
    }
}

// ============================================================
// Final linear: logits[t][n] = b_lin[n] + h2[t]·w_lin[n]
// 64x64 tiles, k-chunks of 32, 256 threads, acc 4x4 per thread.
// ============================================================
__global__ void lin_kernel(const float* __restrict__ w_lin,
                           const float* __restrict__ b_lin) {
    const int n0  = blockIdx.x * 64;
    const int t0  = blockIdx.y * 64;
    const int tid = threadIdx.x;
    const int ti  = tid & 15;   // t sub-index
    const int nj  = tid >> 4;   // n sub-index

    __shared__ float As[64][36];
    __shared__ float Bs[64][36];

    float acc[4][4];
#pragma unroll
    for (int m = 0; m < 4; m++)
#pragma unroll
        for (int n = 0; n < 4; n++) acc[m][n] = 0.f;

    const int lrow = tid >> 2;
    const int lc0  = (tid & 3) * 8;

    for (int kc = 0; kc < HID; kc += 32) {
        {
            const float* src = &g_h[2][t0 + lrow + 1][kc + lc0];
            float4 v0 = *(const float4*)src;
            float4 v1 = *(const float4*)(src + 4);
            *(float4*)&As[lrow][lc0]     = v0;
            *(float4*)&As[lrow][lc0 + 4] = v1;
        }
        {
            int n = n0 + lrow;
            float4 v0 = make_float4(0.f, 0.f, 0.f, 0.f);
            float4 v1 = make_float4(0.f, 0.f, 0.f, 0.f);
            if (n < NSPK) {
                const float* src = &w_lin[n * HID + kc + lc0];
                v0 = *(const float4*)src;
                v1 = *(const float4*)(src + 4);
            }
            *(float4*)&Bs[lrow][lc0]     = v0;
            *(float4*)&Bs[lrow][lc0 + 4] = v1;
        }
        __syncthreads();
#pragma unroll
        for (int kk = 0; kk < 32; kk++) {
            float a[4], b[4];
#pragma unroll
            for (int m = 0; m < 4; m++) a[m] = As[ti + 16 * m][kk];
#pragma unroll
            for (int n = 0; n < 4; n++) b[n] = Bs[nj + 16 * n][kk];
#pragma unroll
            for (int m = 0; m < 4; m++)
#pragma unroll
                for (int n = 0; n < 4; n++)
                    acc[m][n] = fmaf(a[m], b[n], acc[m][n]);
        }
        __syncthreads();
    }
#pragma unroll
    for (int m = 0; m < 4; m++) {
        int t = t0 + ti + 16 * m;
#pragma unroll
        for (int n = 0; n < 4; n++) {
            int nn = n0 + nj + 16 * n;
            if (nn < NSPK) g_logits[t][nn] = acc[m][n] + b_lin[nn];
        }
    }
}

// ============================================================
// Row-wise log_softmax over NSPK, one block per t.
// ============================================================
__global__ void lsm_kernel(float* __restrict__ out) {
    const int t   = blockIdx.x;
    const int tid = threadIdx.x;
    const int lane = tid & 31;
    const int wid  = tid >> 5;

    float v[5];
    float mx = -INFINITY;
#pragma unroll
    for (int m = 0; m < 5; m++) {
        int n = tid + m * 256;
        v[m] = (n < NSPK) ? g_logits[t][n] : -INFINITY;
        mx = fmaxf(mx, v[m]);
    }
    __shared__ float smax[8];
    __shared__ float ssum[8];
#pragma unroll
    for (int o = 16; o > 0; o >>= 1) mx = fmaxf(mx, __shfl_xor_sync(0xffffffffu, mx, o));
    if (lane == 0) smax[wid] = mx;
    __syncthreads();
    mx = smax[0];
#pragma unroll
    for (int w = 1; w < 8; w++) mx = fmaxf(mx, smax[w]);

    float s = 0.f;
#pragma unroll
    for (int m = 0; m < 5; m++) {
        int n = tid + m * 256;
        if (n < NSPK) s += __expf(v[m] - mx);
    }
#pragma unroll
    for (int o = 16; o > 0; o >>= 1) s += __shfl_xor_sync(0xffffffffu, s, o);
    if (lane == 0) ssum[wid] = s;
    __syncthreads();
    s = ssum[0];
#pragma unroll
    for (int w = 1; w < 8; w++) s += ssum[w];

    float lg = logf(s) + mx;
#pragma unroll
    for (int m = 0; m < 5; m++) {
        int n = tid + m * 256;
        if (n < NSPK) out[t * NSPK + n] = v[m] - lg;
    }
}

// ============================================================
extern "C" void kernel_launch(void* const* d_in, const int* in_sizes, int n_in,
                              void* d_out, int out_size) {
    const float* x     = (const float*)d_in[0];
    const float* w_ih0 = (const float*)d_in[1];
    const float* w_hh0 = (const float*)d_in[2];
    const float* b_ih0 = (const float*)d_in[3];
    const float* b_hh0 = (const float*)d_in[4];
    const float* w_ih1 = (const float*)d_in[5];
    const float* w_hh1 = (const float*)d_in[6];
    const float* b_ih1 = (const float*)d_in[7];
    const float* b_hh1 = (const float*)d_in[8];
    const float* w_ih2 = (const float*)d_in[9];
    const float* w_hh2 = (const float*)d_in[10];
    const float* b_ih2 = (const float*)d_in[11];
    const float* b_hh2 = (const float*)d_in[12];
    const float* w_lin = (const float*)d_in[13];
    const float* b_lin = (const float*)d_in[14];

    const int reset_total = 3 * (T_STEPS + 1) * HID;
    reset_kernel<<<(reset_total + 1023) / 1024, 1024>>>();
    xg0_kernel<<<T_STEPS, 256>>>(x, w_ih0, b_ih0, b_hh0);
    lstm_kernel<<<3 * CPL, 256>>>(w_hh0, w_ih1, w_hh1, b_ih1, b_hh1,
                                  w_ih2, w_hh2, b_ih2, b_hh2);
    dim3 gl((NSPK + 63) / 64, T_STEPS / 64);
    lin_kernel<<<gl, 256>>>(w_lin, b_lin);
    lsm_kernel<<<T_STEPS, 256>>>((float*)d_out);
}